// round 4
// baseline (speedup 1.0000x reference)
#include <cuda_runtime.h>

// [R3: resubmit of R2 kernel — previous bench failed on broker infra,
//  f32x2 hypothesis still untested. No functional changes.]
//
// DilatedReparamBlock == single 13x13 depthwise conv + per-channel bias
// (all branches are centered odd-size convs with pad = eff//2).
//
// Stage 1 (prep_kernel): fold 7 branches + BN into equivalent 13x13 weight,
//   stored DUPLICATED as (w,w) float2 pairs with zero rows at top/bottom
//   (15x13 pairs per channel) -> enables packed fma.rn.f32x2 with zero
//   per-thread weight packing cost and branch-free row edges.
// Stage 2 (conv_kernel): fp32 depthwise 13x13 via packed f32x2 FMA.
//   One block per (b,c) image. Thread = 14 cols x 2 rows = 28 outputs,
//   7 packed column-pair accumulators per row. x window loaded as 13
//   aligned LDS64 pairs; odd-kx (shift-by-1) pairs built from register
//   halves (ALU movs, not LSU).

#define CC 256
#define HW 56
#define PAD 6
#define SROWS 68            // 56 + 2*6
#define SSTR  74            // smem row stride (floats), breaks bank collisions
#define NTHR 128

typedef unsigned long long u64;

__device__ u64   g_wdup[CC * 15 * 13];   // (w,w) pairs, rows 0 & 14 are zero
__device__ float g_bias[CC];

static __device__ __forceinline__ void ffma2(u64& acc, u64 x2, u64 w2)
{
    asm("fma.rn.f32x2 %0, %1, %2, %0;" : "+l"(acc) : "l"(x2), "l"(w2));
}

__global__ void prep_kernel(const float* __restrict__ lk_w,
                            const float* __restrict__ w0, const float* __restrict__ w1,
                            const float* __restrict__ w2, const float* __restrict__ w3,
                            const float* __restrict__ w4, const float* __restrict__ w5,
                            const float* __restrict__ gamma, const float* __restrict__ beta,
                            const float* __restrict__ mean,  const float* __restrict__ var)
{
    int c = blockIdx.x;
    int t = threadIdx.x;

    float s[7], sh[7];
#pragma unroll
    for (int i = 0; i < 7; i++) {
        float sc = gamma[i * CC + c] * rsqrtf(var[i * CC + c] + 1e-5f);
        s[i]  = sc;
        sh[i] = beta[i * CC + c] - mean[i * CC + c] * sc;
    }
    if (t == 0)
        g_bias[c] = sh[0] + sh[1] + sh[2] + sh[3] + sh[4] + sh[5] + sh[6];

    if (t < 169) {
        int ty = t / 13, tx = t % 13;
        int dy = ty - PAD, dx = tx - PAD;
        float acc = s[0] * lk_w[c * 169 + t];

        const float* ws[6]   = { w0, w1, w2, w3, w4, w5 };
        const int    KSa[6]  = { 5, 7, 7, 3, 3, 3 };
        const int    DILa[6] = { 1, 1, 2, 3, 4, 5 };
#pragma unroll
        for (int j = 0; j < 6; j++) {
            int r = DILa[j], k = KSa[j];
            if (dy % r == 0 && dx % r == 0) {
                int a  = dy / r + (k - 1) / 2;
                int b2 = dx / r + (k - 1) / 2;
                if (a >= 0 && a < k && b2 >= 0 && b2 < k)
                    acc += s[j + 1] * ws[j][c * k * k + a * k + b2];
            }
        }
        unsigned int u = __float_as_uint(acc);
        g_wdup[c * 195 + (ty + 1) * 13 + tx] = (u64)u | ((u64)u << 32);
    } else if (t < 195) {
        int j   = t - 169;              // 0..25 -> zero rows 0 and 14
        int row = (j < 13) ? 0 : 14;
        int kx  = (j < 13) ? j : j - 13;
        g_wdup[c * 195 + row * 13 + kx] = 0ull;
    }
}

__global__ void __launch_bounds__(NTHR, 4) conv_kernel(const float* __restrict__ x,
                                                       float* __restrict__ out)
{
    __shared__ float sx[SROWS * SSTR];    // ~19.7 KB
    __shared__ u64   swd[15 * 13];        // 1560 B
    __shared__ float sbias;

    int bc = blockIdx.x;
    const float* xim = x   + (size_t)bc * (HW * HW);
    float*       oim = out + (size_t)bc * (HW * HW);
    int tid = threadIdx.x;
    int c   = bc & (CC - 1);

    // Padded 68x68 tile (zero halo), coalesced fill.
    for (int idx = tid; idx < SROWS * SROWS; idx += NTHR) {
        int r   = idx / SROWS;
        int cc2 = idx - r * SROWS;
        int iy = r - PAD, ix = cc2 - PAD;
        float v = 0.f;
        if ((unsigned)iy < (unsigned)HW && (unsigned)ix < (unsigned)HW)
            v = xim[iy * HW + ix];
        sx[r * SSTR + cc2] = v;
    }
    for (int t = tid; t < 195; t += NTHR) swd[t] = g_wdup[c * 195 + t];
    if (tid == 0) sbias = g_bias[c];
    __syncthreads();

    int colb = tid & 3;                 // 0..3  -> ox0 = colb*14
    int pr   = tid >> 2;                // 0..31 -> oy0 = pr*2 (pr<28 active)
    if (pr >= 28) return;
    int oy0 = pr * 2;
    int ox0 = colb * 14;

    u64 acc0[7], acc1[7];
#pragma unroll
    for (int p = 0; p < 7; p++) { acc0[p] = 0ull; acc1[p] = 0ull; }

    // Input row iy feeds: out row0 with weight row iy, out row1 with row iy-1.
    // swd row r+1 holds weight row r; rows 0 and 14 are zeros -> no branches.
#pragma unroll 1
    for (int iy = 0; iy < 14; iy++) {
        const u64* xrow = reinterpret_cast<const u64*>(&sx[(oy0 + iy) * SSTR + ox0]);
        u64 xe[13];
#pragma unroll
        for (int i = 0; i < 13; i++) xe[i] = xrow[i];
        u64 xs[12];                      // window shifted by one float
#pragma unroll
        for (int i = 0; i < 12; i++) xs[i] = (xe[i] >> 32) | (xe[i + 1] << 32);

        const u64* wr0 = &swd[(iy + 1) * 13];
        const u64* wr1 = &swd[iy * 13];
#pragma unroll
        for (int kx = 0; kx < 13; kx++) {
            u64 w0 = wr0[kx];
            u64 w1 = wr1[kx];
#pragma unroll
            for (int p = 0; p < 7; p++) {
                u64 x2 = (kx & 1) ? xs[((kx - 1) >> 1) + p] : xe[(kx >> 1) + p];
                ffma2(acc0[p], x2, w0);
                ffma2(acc1[p], x2, w1);
            }
        }
    }

    float bb = sbias;
    float2* o0 = reinterpret_cast<float2*>(&oim[oy0 * HW + ox0]);
    float2* o1 = reinterpret_cast<float2*>(&oim[(oy0 + 1) * HW + ox0]);
#pragma unroll
    for (int p = 0; p < 7; p++) {
        float2 r0 = make_float2(__uint_as_float((unsigned)acc0[p]) + bb,
                                __uint_as_float((unsigned)(acc0[p] >> 32)) + bb);
        float2 r1 = make_float2(__uint_as_float((unsigned)acc1[p]) + bb,
                                __uint_as_float((unsigned)(acc1[p] >> 32)) + bb);
        o0[p] = r0;
        o1[p] = r1;
    }
}

extern "C" void kernel_launch(void* const* d_in, const int* in_sizes, int n_in,
                              void* d_out, int out_size)
{
    const float* x    = (const float*)d_in[0];
    const float* lk_w = (const float*)d_in[1];
    const float* w0   = (const float*)d_in[2];
    const float* w1   = (const float*)d_in[3];
    const float* w2   = (const float*)d_in[4];
    const float* w3   = (const float*)d_in[5];
    const float* w4   = (const float*)d_in[6];
    const float* w5   = (const float*)d_in[7];
    const float* g    = (const float*)d_in[8];
    const float* b    = (const float*)d_in[9];
    const float* m    = (const float*)d_in[10];
    const float* v    = (const float*)d_in[11];
    float* out = (float*)d_out;

    prep_kernel<<<CC, 256>>>(lk_w, w0, w1, w2, w3, w4, w5, g, b, m, v);

    int nimg = out_size / (HW * HW);    // 8192
    conv_kernel<<<nimg, NTHR>>>(x, out);
}

// round 5
// speedup vs baseline: 1.1784x; 1.1784x over previous
#include <cuda_runtime.h>

// DilatedReparamBlock == single 13x13 depthwise conv + per-channel bias.
//
// R4: f32x2 packed FMA, take 2. R3's register-half shuffling drowned the ALU
// pipe (45.6%) and throttled issue. Now EVERY FFMA2 operand is a direct
// aligned LDS.64: a second smem tile shifted by one column (sx2) supplies the
// odd-kx pairs. Zero ALU packing in the mainloop.

#define CC 256
#define HW 56
#define PAD 6
#define SROWS 68            // 56 + 2*6
#define SSTR  74            // row stride in floats (even -> u64-aligned rows)
#define NTHR 128

typedef unsigned long long u64;

__device__ u64   g_wdup[CC * 15 * 13];   // (w,w) pairs; rows 0 & 14 zero
__device__ float g_bias[CC];

static __device__ __forceinline__ void ffma2(u64& acc, u64 x2, u64 w2)
{
    asm("fma.rn.f32x2 %0, %1, %2, %0;" : "+l"(acc) : "l"(x2), "l"(w2));
}

__global__ void prep_kernel(const float* __restrict__ lk_w,
                            const float* __restrict__ w0, const float* __restrict__ w1,
                            const float* __restrict__ w2, const float* __restrict__ w3,
                            const float* __restrict__ w4, const float* __restrict__ w5,
                            const float* __restrict__ gamma, const float* __restrict__ beta,
                            const float* __restrict__ mean,  const float* __restrict__ var)
{
    int c = blockIdx.x;
    int t = threadIdx.x;

    float s[7], sh[7];
#pragma unroll
    for (int i = 0; i < 7; i++) {
        float sc = gamma[i * CC + c] * rsqrtf(var[i * CC + c] + 1e-5f);
        s[i]  = sc;
        sh[i] = beta[i * CC + c] - mean[i * CC + c] * sc;
    }
    if (t == 0)
        g_bias[c] = sh[0] + sh[1] + sh[2] + sh[3] + sh[4] + sh[5] + sh[6];

    if (t < 169) {
        int ty = t / 13, tx = t % 13;
        int dy = ty - PAD, dx = tx - PAD;
        float acc = s[0] * lk_w[c * 169 + t];

        const float* ws[6]   = { w0, w1, w2, w3, w4, w5 };
        const int    KSa[6]  = { 5, 7, 7, 3, 3, 3 };
        const int    DILa[6] = { 1, 1, 2, 3, 4, 5 };
#pragma unroll
        for (int j = 0; j < 6; j++) {
            int r = DILa[j], k = KSa[j];
            if (dy % r == 0 && dx % r == 0) {
                int a  = dy / r + (k - 1) / 2;
                int b2 = dx / r + (k - 1) / 2;
                if (a >= 0 && a < k && b2 >= 0 && b2 < k)
                    acc += s[j + 1] * ws[j][c * k * k + a * k + b2];
            }
        }
        unsigned int u = __float_as_uint(acc);
        g_wdup[c * 195 + (ty + 1) * 13 + tx] = (u64)u | ((u64)u << 32);
    } else if (t < 195) {
        int j   = t - 169;
        int row = (j < 13) ? 0 : 14;
        int kx  = (j < 13) ? j : j - 13;
        g_wdup[c * 195 + row * 13 + kx] = 0ull;
    }
}

__global__ void __launch_bounds__(NTHR, 4) conv_kernel(const float* __restrict__ x,
                                                       float* __restrict__ out)
{
    __shared__ float sx [SROWS * SSTR];   // X(r,c): padded tile
    __shared__ float sx2[SROWS * SSTR];   // X(r,c+1): shifted copy
    __shared__ u64   swd[15 * 13];
    __shared__ float sbias;

    int bc = blockIdx.x;
    const float* xim = x   + (size_t)bc * (HW * HW);
    float*       oim = out + (size_t)bc * (HW * HW);
    int tid = threadIdx.x;
    int c   = bc & (CC - 1);

    // Fill both tiles (coalesced; second pass hits L1).
    for (int idx = tid; idx < SROWS * SROWS; idx += NTHR) {
        int r   = idx / SROWS;
        int cc2 = idx - r * SROWS;
        int iy = r - PAD, ix = cc2 - PAD;
        float v = 0.f;
        if ((unsigned)iy < (unsigned)HW && (unsigned)ix < (unsigned)HW)
            v = xim[iy * HW + ix];
        sx[r * SSTR + cc2] = v;

        int ix2 = cc2 - PAD + 1;                 // X(r, cc2+1)
        float v2 = 0.f;
        if ((unsigned)iy < (unsigned)HW && (unsigned)ix2 < (unsigned)HW)
            v2 = xim[iy * HW + ix2];
        sx2[r * SSTR + cc2] = v2;
    }
    for (int t = tid; t < 195; t += NTHR) swd[t] = g_wdup[c * 195 + t];
    if (tid == 0) sbias = g_bias[c];
    __syncthreads();

    int colb = tid & 3;                 // ox0 = colb*14  (even -> aligned)
    int pr   = tid >> 2;                // oy0 = pr*2, pr<28 active
    if (pr >= 28) return;
    int oy0 = pr * 2;
    int ox0 = colb * 14;

    u64 acc0[7], acc1[7];
#pragma unroll
    for (int p = 0; p < 7; p++) { acc0[p] = 0ull; acc1[p] = 0ull; }

    // Input row iy -> out row0 (weight row iy) + out row1 (weight row iy-1).
#pragma unroll 1
    for (int iy = 0; iy < 14; iy++) {
        const u64* er = reinterpret_cast<const u64*>(&sx [(oy0 + iy) * SSTR + ox0]);
        const u64* sr = reinterpret_cast<const u64*>(&sx2[(oy0 + iy) * SSTR + ox0]);
        u64 xe[13], xo[12];
#pragma unroll
        for (int i = 0; i < 13; i++) xe[i] = er[i];
#pragma unroll
        for (int i = 0; i < 12; i++) xo[i] = sr[i];

        const u64* wr0 = &swd[(iy + 1) * 13];
        const u64* wr1 = &swd[iy * 13];
#pragma unroll
        for (int kx = 0; kx < 13; kx++) {
            u64 w0 = wr0[kx];
            u64 w1 = wr1[kx];
#pragma unroll
            for (int p = 0; p < 7; p++) {
                u64 x2 = (kx & 1) ? xo[((kx - 1) >> 1) + p] : xe[(kx >> 1) + p];
                ffma2(acc0[p], x2, w0);
                ffma2(acc1[p], x2, w1);
            }
        }
    }

    float bb = sbias;
    float2* o0 = reinterpret_cast<float2*>(&oim[oy0 * HW + ox0]);
    float2* o1 = reinterpret_cast<float2*>(&oim[(oy0 + 1) * HW + ox0]);
#pragma unroll
    for (int p = 0; p < 7; p++) {
        float2 r0 = make_float2(__uint_as_float((unsigned)acc0[p]) + bb,
                                __uint_as_float((unsigned)(acc0[p] >> 32)) + bb);
        float2 r1 = make_float2(__uint_as_float((unsigned)acc1[p]) + bb,
                                __uint_as_float((unsigned)(acc1[p] >> 32)) + bb);
        o0[p] = r0;
        o1[p] = r1;
    }
}

extern "C" void kernel_launch(void* const* d_in, const int* in_sizes, int n_in,
                              void* d_out, int out_size)
{
    const float* x    = (const float*)d_in[0];
    const float* lk_w = (const float*)d_in[1];
    const float* w0   = (const float*)d_in[2];
    const float* w1   = (const float*)d_in[3];
    const float* w2   = (const float*)d_in[4];
    const float* w3   = (const float*)d_in[5];
    const float* w4   = (const float*)d_in[6];
    const float* w5   = (const float*)d_in[7];
    const float* g    = (const float*)d_in[8];
    const float* b    = (const float*)d_in[9];
    const float* m    = (const float*)d_in[10];
    const float* v    = (const float*)d_in[11];
    float* out = (float*)d_out;

    prep_kernel<<<CC, 256>>>(lk_w, w0, w1, w2, w3, w4, w5, g, b, m, v);

    int nimg = out_size / (HW * HW);    // 8192
    conv_kernel<<<nimg, NTHR>>>(x, out);
}